// round 1
// baseline (speedup 1.0000x reference)
#include <cuda_runtime.h>

#define HW 16384
#define IMG 128

// ---------------- scratch (static __device__, no allocs) ----------------
__device__ float g_t[8L * 384 * HW];   // pos-conv output (B,384,H,W)
__device__ float g_q[8L * 128 * HW];   // q channels
__device__ float g_k[8L * 128 * HW];   // k channels
__device__ float g_y[8L * 256 * HW];   // [v(128) | d3(64) | d5(64)]
__device__ float g_A[8 * 128 * 256];   // per-batch folded proj*attn matrix
__device__ float g_gram[64 * 288];     // per (b,h): G[256], qn[16], kn[16]

// ---------------- zero gram accumulators ----------------
__global__ void zero_gram_k() {
    int i = blockIdx.x * 256 + threadIdx.x;
    if (i < 64 * 288) g_gram[i] = 0.f;
}

// ---------------- generic SGEMM: C[b](M x 16384) = A(M x K) @ B[b](K x 16384) (+bias) ----
// 64x128 CTA tile, 128 threads, 8x8 register tile per thread.
template <int K>
__device__ __forceinline__ void sgemm_body(
    const float* __restrict__ A, const float* __restrict__ B,
    float* __restrict__ C, const float* __restrict__ bias,
    long aB, long bB, long cB)
{
    __shared__ float As[16][66];
    __shared__ float Bs[16][128];
    const int b = blockIdx.z;
    const float* Ab = A + (long)b * aB;
    const float* Bb = B + (long)b * bB;
    float* Cb = C + (long)b * cB;
    const int m0 = blockIdx.y * 64;
    const int n0 = blockIdx.x * 128;
    const int tid = threadIdx.x;
    const int tx = tid & 15, ty = tid >> 4;

    float acc[8][8];
#pragma unroll
    for (int i = 0; i < 8; i++)
#pragma unroll
        for (int j = 0; j < 8; j++) acc[i][j] = 0.f;

    for (int k0 = 0; k0 < K; k0 += 16) {
        // A tile 64x16 -> transposed into As[k][m]
#pragma unroll
        for (int t = 0; t < 2; t++) {
            int idx = tid + t * 128;            // 0..255
            int row = idx >> 2;                 // 0..63
            int kc  = (idx & 3) << 2;           // 0,4,8,12
            float4 v = *(const float4*)(Ab + (long)(m0 + row) * K + k0 + kc);
            As[kc + 0][row] = v.x; As[kc + 1][row] = v.y;
            As[kc + 2][row] = v.z; As[kc + 3][row] = v.w;
        }
        // B tile 16x128
#pragma unroll
        for (int t = 0; t < 4; t++) {
            int idx = tid + t * 128;            // 0..511
            int row = idx >> 5;                 // 0..15
            int c   = (idx & 31) << 2;          // 0..124
            *(float4*)(&Bs[row][c]) =
                *(const float4*)(Bb + (long)(k0 + row) * HW + n0 + c);
        }
        __syncthreads();
#pragma unroll
        for (int kk = 0; kk < 16; kk++) {
            float a[8], bb[8];
#pragma unroll
            for (int i = 0; i < 8; i++) a[i] = As[kk][ty * 8 + i];
#pragma unroll
            for (int j = 0; j < 8; j++) bb[j] = Bs[kk][tx * 8 + j];
#pragma unroll
            for (int i = 0; i < 8; i++)
#pragma unroll
                for (int j = 0; j < 8; j++) acc[i][j] += a[i] * bb[j];
        }
        __syncthreads();
    }
#pragma unroll
    for (int i = 0; i < 8; i++) {
        float bv = bias ? bias[m0 + ty * 8 + i] : 0.f;
        float* cp = Cb + (long)(m0 + ty * 8 + i) * HW + n0 + tx * 8;
        float4 v0 = make_float4(acc[i][0] + bv, acc[i][1] + bv, acc[i][2] + bv, acc[i][3] + bv);
        float4 v1 = make_float4(acc[i][4] + bv, acc[i][5] + bv, acc[i][6] + bv, acc[i][7] + bv);
        *(float4*)cp = v0;
        *(float4*)(cp + 4) = v1;
    }
}

__global__ __launch_bounds__(128) void k1_gemm(
    const float* __restrict__ x, const float* __restrict__ pw, const float* __restrict__ pb)
{
    sgemm_body<128>(pw, x, g_t, pb, 0L, 128L * HW, 384L * HW);
}

__global__ __launch_bounds__(128) void k4_gemm(float* __restrict__ out)
{
    sgemm_body<256>(g_A, g_y, out, nullptr, 128L * 256, 256L * HW, 128L * HW);
}

// ---------------- dual grouped conv (3x3 + 5x5 sharing input pair) ----------------
// MODE 0: in = g_t (384 ch, 192 groups) -> q / k / v routing
// MODE 1: in = x   (128 ch,  64 groups) -> y[128..191] (3x3), y[192..255] (5x5)
template <int MODE>
__global__ __launch_bounds__(256) void dualconv_k(
    const float* __restrict__ in_ext,
    const float* __restrict__ w3, const float* __restrict__ b3,
    const float* __restrict__ w5, const float* __restrict__ b5)
{
    const int Cin = (MODE == 0) ? 384 : 128;
    const float* in = (MODE == 0) ? (const float*)g_t : in_ext;

    __shared__ float s[2 * 68 * 68];
    __shared__ float sw[68];

    const int tile = blockIdx.x;                 // 0..3 (2x2 tiles of 64x64)
    const int oy0 = (tile >> 1) * 64;
    const int ox0 = (tile & 1) * 64;
    const int g0 = blockIdx.y * 16;
    const long bz = blockIdx.z;
    const int tid = threadIdx.x;
    const int ttx = tid & 15, tty = tid >> 4;    // 16x16 threads, 4x4 px each
    const int py0 = tty * 4, px0 = ttx * 4;

    for (int g = g0; g < g0 + 16; ++g) {
        const float* in0 = in + (bz * Cin + 2 * g) * (long)HW;
        // load 2-channel halo tile 68x68
        for (int idx = tid; idx < 2 * 68 * 68; idx += 256) {
            int ch = idx / 4624;
            int rem = idx - ch * 4624;
            int r = rem / 68, cc = rem - r * 68;
            int gy = oy0 - 2 + r, gx = ox0 - 2 + cc;
            float v = 0.f;
            if ((unsigned)gy < 128u && (unsigned)gx < 128u)
                v = in0[ch * HW + gy * IMG + gx];
            s[idx] = v;
        }
        if (tid < 50) sw[tid] = w5[g * 50 + tid];
        else if (tid < 68) sw[tid] = w3[g * 18 + (tid - 50)];
        __syncthreads();

        float a3[4][4], a5[4][4];
#pragma unroll
        for (int i = 0; i < 4; i++)
#pragma unroll
            for (int j = 0; j < 4; j++) { a3[i][j] = 0.f; a5[i][j] = 0.f; }

#pragma unroll
        for (int ic = 0; ic < 2; ++ic) {
            const float* sc = s + ic * 4624 + py0 * 68 + px0;
            float r[8][8];
#pragma unroll
            for (int dy = 0; dy < 8; dy++)
#pragma unroll
                for (int dx = 0; dx < 8; dx++) r[dy][dx] = sc[dy * 68 + dx];
            const float* w5s = sw + ic * 25;
#pragma unroll
            for (int t = 0; t < 25; t++) {
                float wv = w5s[t];
                int ky = t / 5, kx = t % 5;
#pragma unroll
                for (int oy = 0; oy < 4; oy++)
#pragma unroll
                    for (int ox = 0; ox < 4; ox++)
                        a5[oy][ox] += r[oy + ky][ox + kx] * wv;
            }
            const float* w3s = sw + 50 + ic * 9;
#pragma unroll
            for (int t = 0; t < 9; t++) {
                float wv = w3s[t];
                int ky = t / 3, kx = t % 3;
#pragma unroll
                for (int oy = 0; oy < 4; oy++)
#pragma unroll
                    for (int ox = 0; ox < 4; ox++)
                        a3[oy][ox] += r[oy + 1 + ky][ox + 1 + kx] * wv;
            }
        }

        float bias3 = b3[g], bias5 = b5[g];
        float *dst3, *dst5;
        if (MODE == 0) {
            dst3 = (g < 128) ? &g_q[(bz * 128 + g) * HW]
                             : &g_k[(bz * 128 + (g - 128)) * HW];
            dst5 = (g < 64)  ? &g_k[(bz * 128 + 64 + g) * HW]
                             : &g_y[(bz * 256 + (g - 64)) * HW];
        } else {
            dst3 = &g_y[(bz * 256 + 128 + g) * HW];
            dst5 = &g_y[(bz * 256 + 192 + g) * HW];
        }
#pragma unroll
        for (int oy = 0; oy < 4; oy++) {
            int off = (oy0 + py0 + oy) * IMG + ox0 + px0;
            float4 v3 = make_float4(a3[oy][0] + bias3, a3[oy][1] + bias3,
                                    a3[oy][2] + bias3, a3[oy][3] + bias3);
            float4 v5 = make_float4(a5[oy][0] + bias5, a5[oy][1] + bias5,
                                    a5[oy][2] + bias5, a5[oy][3] + bias5);
            *(float4*)(dst3 + off) = v3;
            *(float4*)(dst5 + off) = v5;
        }
        __syncthreads();
    }
}

// ---------------- gram: per (b,h): G[16][16] = q @ k^T over pixels + sq norms ------
__global__ __launch_bounds__(256) void gram_k()
{
    const int bh = blockIdx.x;           // 0..63
    const int slice = blockIdx.y;        // 0..15 (1024 px each)
    const int b = bh >> 3, h = bh & 7;
    const float* qp = g_q + (long)(b * 128 + h * 16) * HW + slice * 1024;
    const float* kp = g_k + (long)(b * 128 + h * 16) * HW + slice * 1024;

    __shared__ float sq[64][17];
    __shared__ float sk[64][17];
    const int tid = threadIdx.x;
    const int phase = tid & 15, dg = (tid >> 4) & 3, eg = tid >> 6;

    float acc[4][4], aq[4], ak[4];
#pragma unroll
    for (int i = 0; i < 4; i++) {
        aq[i] = 0.f; ak[i] = 0.f;
#pragma unroll
        for (int j = 0; j < 4; j++) acc[i][j] = 0.f;
    }

    for (int blk = 0; blk < 16; ++blk) {
        for (int idx = tid; idx < 1024; idx += 256) {
            int d = idx >> 6, p = idx & 63;
            sq[p][d] = qp[(long)d * HW + blk * 64 + p];
            sk[p][d] = kp[(long)d * HW + blk * 64 + p];
        }
        __syncthreads();
        for (int p = phase; p < 64; p += 16) {
            float qv[4], kv[4];
#pragma unroll
            for (int i = 0; i < 4; i++) qv[i] = sq[p][dg * 4 + i];
#pragma unroll
            for (int j = 0; j < 4; j++) kv[j] = sk[p][eg * 4 + j];
#pragma unroll
            for (int i = 0; i < 4; i++)
#pragma unroll
                for (int j = 0; j < 4; j++) acc[i][j] += qv[i] * kv[j];
            if (eg == 0) {
#pragma unroll
                for (int i = 0; i < 4; i++) aq[i] += qv[i] * qv[i];
            }
            if (dg == 0) {
#pragma unroll
                for (int j = 0; j < 4; j++) ak[j] += kv[j] * kv[j];
            }
        }
        __syncthreads();
    }

    __shared__ float sG[288];
    for (int idx = tid; idx < 288; idx += 256) sG[idx] = 0.f;
    __syncthreads();
#pragma unroll
    for (int i = 0; i < 4; i++)
#pragma unroll
        for (int j = 0; j < 4; j++)
            atomicAdd(&sG[(dg * 4 + i) * 16 + eg * 4 + j], acc[i][j]);
    if (eg == 0) {
#pragma unroll
        for (int i = 0; i < 4; i++) atomicAdd(&sG[256 + dg * 4 + i], aq[i]);
    }
    if (dg == 0) {
#pragma unroll
        for (int j = 0; j < 4; j++) atomicAdd(&sG[272 + eg * 4 + j], ak[j]);
    }
    __syncthreads();
    float* gg = g_gram + bh * 288;
    for (int idx = tid; idx < 288; idx += 256) atomicAdd(gg + idx, sG[idx]);
}

// ---------------- attn: normalize gram, softmax, fold with proj into g_A ----------
__global__ __launch_bounds__(256) void attn_k(
    const float* __restrict__ temp, const float* __restrict__ proj_w)
{
    const int b = blockIdx.x;
    const int part = blockIdx.y;
    const int tid = threadIdx.x;
    float* dstA = g_A + (long)b * 128 * 256;

    if (part == 8) {  // copy proj tail columns (same for all batches)
        for (int idx = tid; idx < 128 * 128; idx += 256) {
            int c = idx >> 7, j = idx & 127;
            dstA[c * 256 + 128 + j] = proj_w[c * 256 + 128 + j];
        }
        return;
    }
    const int h = part;
    const float* gg = g_gram + (b * 8 + h) * 288;
    __shared__ float sA[256], sqn[16], skn[16], srm[16], srs[16];
    if (tid < 16) {
        sqn[tid] = fmaxf(sqrtf(gg[256 + tid]), 1e-12f);
        skn[tid] = fmaxf(sqrtf(gg[272 + tid]), 1e-12f);
    }
    __syncthreads();
    const int d = tid >> 4, e = tid & 15;
    float val = gg[d * 16 + e] / (sqn[d] * skn[e]) * temp[h];
    sA[tid] = val;
    __syncthreads();
    if (e == 0) {
        float m = -1e30f;
        for (int j = 0; j < 16; j++) m = fmaxf(m, sA[d * 16 + j]);
        srm[d] = m;
    }
    __syncthreads();
    float p = expf(val - srm[d]);
    sA[tid] = p;
    __syncthreads();
    if (e == 0) {
        float ssum = 0.f;
        for (int j = 0; j < 16; j++) ssum += sA[d * 16 + j];
        srs[d] = ssum;
    }
    __syncthreads();
    sA[tid] = p / srs[d];
    __syncthreads();
    // fold: A[c][h*16+e] = sum_d proj[c][h*16+d] * attn[d][e]
    for (int o = tid; o < 2048; o += 256) {
        int c = o >> 4, ee = o & 15;
        float accv = 0.f;
#pragma unroll
        for (int dd = 0; dd < 16; dd++)
            accv += proj_w[c * 256 + h * 16 + dd] * sA[dd * 16 + ee];
        dstA[c * 256 + h * 16 + ee] = accv;
    }
}

// ---------------- launch ----------------
extern "C" void kernel_launch(void* const* d_in, const int* in_sizes, int n_in,
                              void* d_out, int out_size)
{
    const float* x      = (const float*)d_in[0];
    const float* pos_w  = (const float*)d_in[1];
    const float* pos_b  = (const float*)d_in[2];
    const float* qd3_w  = (const float*)d_in[3];
    const float* qd3_b  = (const float*)d_in[4];
    const float* qd5_w  = (const float*)d_in[5];
    const float* qd5_b  = (const float*)d_in[6];
    const float* temp   = (const float*)d_in[7];
    const float* d3_w   = (const float*)d_in[8];
    const float* d3_b   = (const float*)d_in[9];
    const float* d5_w   = (const float*)d_in[10];
    const float* d5_b   = (const float*)d_in[11];
    const float* proj_w = (const float*)d_in[12];
    float* out = (float*)d_out;

    zero_gram_k<<<72, 256>>>();
    k1_gemm<<<dim3(128, 6, 8), 128>>>(x, pos_w, pos_b);
    dualconv_k<0><<<dim3(4, 12, 8), 256>>>(nullptr, qd3_w, qd3_b, qd5_w, qd5_b);
    dualconv_k<1><<<dim3(4, 4, 8), 256>>>(x, d3_w, d3_b, d5_w, d5_b);
    gram_k<<<dim3(64, 16), 256>>>();
    attn_k<<<dim3(8, 9), 256>>>(temp, proj_w);
    k4_gemm<<<dim3(128, 2, 8), 128>>>(out);
}

// round 4
// speedup vs baseline: 1.1946x; 1.1946x over previous
#include <cuda_runtime.h>

#define HW 16384
#define IMG 128

// ---------------- scratch (static __device__, no allocs) ----------------
__device__ float g_t[8L * 384 * HW];   // pos-conv output (B,384,H,W)
__device__ float g_q[8L * 128 * HW];   // q channels
__device__ float g_k[8L * 128 * HW];   // k channels
__device__ float g_y[8L * 256 * HW];   // [v(128) | d3(64) | d5(64)]
__device__ float g_A[8 * 128 * 256];   // per-batch folded proj*attn matrix
__device__ float g_gram[64 * 288];     // per (b,h): G[256], qn[16], kn[16]

// ---------------- zero gram accumulators ----------------
__global__ void zero_gram_k() {
    int i = blockIdx.x * 256 + threadIdx.x;
    if (i < 64 * 288) g_gram[i] = 0.f;
}

// ---------------- SGEMM: C[b](M x 16384) = A(M x K) @ B[b](K x 16384) (+bias) ----
// 128x128 CTA tile, 256 threads, 8x8 per thread, double-buffered smem.
template <int K>
__device__ __forceinline__ void sgemm_body(
    const float* __restrict__ A, const float* __restrict__ B,
    float* __restrict__ C, const float* __restrict__ bias,
    long aB, long bB, long cB)
{
    __shared__ float As[2][16][132];
    __shared__ float Bs[2][16][128];
    const int b = blockIdx.z;
    const float* Ab = A + (long)b * aB;
    const float* Bb = B + (long)b * bB;
    float* Cb = C + (long)b * cB;
    const int m0 = blockIdx.y * 128;
    const int n0 = blockIdx.x * 128;
    const int tid = threadIdx.x;
    const int tx = tid & 15, ty = tid >> 4;

    const int arow = tid >> 2, akc = (tid & 3) << 2;   // A: 64 rows per t-pass
    const int brow = tid >> 5, bcol = (tid & 31) << 2; // B: 8 rows per t-pass

    float acc[8][8];
#pragma unroll
    for (int i = 0; i < 8; i++)
#pragma unroll
        for (int j = 0; j < 8; j++) acc[i][j] = 0.f;

    float4 ra[2], rb[2];
#pragma unroll
    for (int t = 0; t < 2; t++)
        ra[t] = *(const float4*)(Ab + (long)(m0 + arow + t * 64) * K + akc);
#pragma unroll
    for (int t = 0; t < 2; t++)
        rb[t] = *(const float4*)(Bb + (long)(brow + t * 8) * HW + n0 + bcol);

    int buf = 0;
#pragma unroll
    for (int t = 0; t < 2; t++) {
        int row = arow + t * 64;
        As[0][akc + 0][row] = ra[t].x; As[0][akc + 1][row] = ra[t].y;
        As[0][akc + 2][row] = ra[t].z; As[0][akc + 3][row] = ra[t].w;
        *(float4*)(&Bs[0][brow + t * 8][bcol]) = rb[t];
    }
    __syncthreads();

    const int NS = K / 16;
    for (int s = 0; s < NS; s++) {
        if (s + 1 < NS) {
            int k0 = (s + 1) * 16;
#pragma unroll
            for (int t = 0; t < 2; t++)
                ra[t] = *(const float4*)(Ab + (long)(m0 + arow + t * 64) * K + k0 + akc);
#pragma unroll
            for (int t = 0; t < 2; t++)
                rb[t] = *(const float4*)(Bb + (long)(k0 + brow + t * 8) * HW + n0 + bcol);
        }
#pragma unroll
        for (int kk = 0; kk < 16; kk++) {
            float4 a0 = *(const float4*)&As[buf][kk][ty * 8];
            float4 a1 = *(const float4*)&As[buf][kk][ty * 8 + 4];
            float4 b0 = *(const float4*)&Bs[buf][kk][tx * 8];
            float4 b1 = *(const float4*)&Bs[buf][kk][tx * 8 + 4];
            float av[8] = { a0.x, a0.y, a0.z, a0.w, a1.x, a1.y, a1.z, a1.w };
            float bv[8] = { b0.x, b0.y, b0.z, b0.w, b1.x, b1.y, b1.z, b1.w };
#pragma unroll
            for (int i = 0; i < 8; i++)
#pragma unroll
                for (int j = 0; j < 8; j++)
                    acc[i][j] = fmaf(av[i], bv[j], acc[i][j]);
        }
        if (s + 1 < NS) {
            int nb = buf ^ 1;
#pragma unroll
            for (int t = 0; t < 2; t++) {
                int row = arow + t * 64;
                As[nb][akc + 0][row] = ra[t].x; As[nb][akc + 1][row] = ra[t].y;
                As[nb][akc + 2][row] = ra[t].z; As[nb][akc + 3][row] = ra[t].w;
                *(float4*)(&Bs[nb][brow + t * 8][bcol]) = rb[t];
            }
            __syncthreads();
            buf = nb;
        }
    }

#pragma unroll
    for (int i = 0; i < 8; i++) {
        float bv = bias ? bias[m0 + ty * 8 + i] : 0.f;
        float* cp = Cb + (long)(m0 + ty * 8 + i) * HW + n0 + tx * 8;
        *(float4*)cp = make_float4(acc[i][0] + bv, acc[i][1] + bv,
                                   acc[i][2] + bv, acc[i][3] + bv);
        *(float4*)(cp + 4) = make_float4(acc[i][4] + bv, acc[i][5] + bv,
                                         acc[i][6] + bv, acc[i][7] + bv);
    }
}

__global__ __launch_bounds__(256) void k1_gemm(
    const float* __restrict__ x, const float* __restrict__ pw, const float* __restrict__ pb)
{
    sgemm_body<128>(pw, x, g_t, pb, 0L, 128L * HW, 384L * HW);
}

__global__ __launch_bounds__(256) void k4_gemm(float* __restrict__ out)
{
    sgemm_body<256>(g_A, g_y, out, nullptr, 128L * 256, 256L * HW, 128L * HW);
}

// ---------------- dual grouped conv (3x3 + 5x5 sharing input pair) ----------------
// One group per CTA (grid.y = groups). MODE 0: in = g_t (192 groups) -> q/k/v.
// MODE 1: in = x (64 groups) -> y[128..191] (3x3), y[192..255] (5x5)
template <int MODE>
__global__ __launch_bounds__(256) void dualconv_k(
    const float* __restrict__ in_ext,
    const float* __restrict__ w3, const float* __restrict__ b3,
    const float* __restrict__ w5, const float* __restrict__ b5)
{
    const int Cin = (MODE == 0) ? 384 : 128;
    const float* in = (MODE == 0) ? (const float*)g_t : in_ext;

    __shared__ float s[2 * 68 * 68];
    __shared__ float sw[68];

    const int tile = blockIdx.x;                 // 0..3 (2x2 tiles of 64x64)
    const int oy0 = (tile >> 1) * 64;
    const int ox0 = (tile & 1) * 64;
    const int g = blockIdx.y;
    const long bz = blockIdx.z;
    const int tid = threadIdx.x;
    const int ttx = tid & 15, tty = tid >> 4;    // 16x16 threads, 4x4 px each
    const int py0 = tty * 4, px0 = ttx * 4;

    const float* in0 = in + (bz * Cin + 2 * g) * (long)HW;
    // load 2-channel halo tile 68x68
    for (int idx = tid; idx < 2 * 68 * 68; idx += 256) {
        int ch = idx / 4624;
        int rem = idx - ch * 4624;
        int r = rem / 68, cc = rem - r * 68;
        int gy = oy0 - 2 + r, gx = ox0 - 2 + cc;
        float v = 0.f;
        if ((unsigned)gy < 128u && (unsigned)gx < 128u)
            v = in0[ch * HW + gy * IMG + gx];
        s[idx] = v;
    }
    if (tid < 50) sw[tid] = w5[g * 50 + tid];
    else if (tid < 68) sw[tid] = w3[g * 18 + (tid - 50)];
    __syncthreads();

    float a3[4][4], a5[4][4];
#pragma unroll
    for (int i = 0; i < 4; i++)
#pragma unroll
        for (int j = 0; j < 4; j++) { a3[i][j] = 0.f; a5[i][j] = 0.f; }

#pragma unroll
    for (int ic = 0; ic < 2; ++ic) {
        const float* sc = s + ic * 4624 + py0 * 68 + px0;
        float r[8][8];
#pragma unroll
        for (int dy = 0; dy < 8; dy++)
#pragma unroll
            for (int dx = 0; dx < 8; dx++) r[dy][dx] = sc[dy * 68 + dx];
        const float* w5s = sw + ic * 25;
#pragma unroll
        for (int t = 0; t < 25; t++) {
            float wv = w5s[t];
            int ky = t / 5, kx = t % 5;
#pragma unroll
            for (int oy = 0; oy < 4; oy++)
#pragma unroll
                for (int ox = 0; ox < 4; ox++)
                    a5[oy][ox] += r[oy + ky][ox + kx] * wv;
        }
        const float* w3s = sw + 50 + ic * 9;
#pragma unroll
        for (int t = 0; t < 9; t++) {
            float wv = w3s[t];
            int ky = t / 3, kx = t % 3;
#pragma unroll
            for (int oy = 0; oy < 4; oy++)
#pragma unroll
                for (int ox = 0; ox < 4; ox++)
                    a3[oy][ox] += r[oy + 1 + ky][ox + 1 + kx] * wv;
        }
    }

    float bias3 = b3[g], bias5 = b5[g];
    float *dst3, *dst5;
    if (MODE == 0) {
        dst3 = (g < 128) ? &g_q[(bz * 128 + g) * HW]
                         : &g_k[(bz * 128 + (g - 128)) * HW];
        dst5 = (g < 64)  ? &g_k[(bz * 128 + 64 + g) * HW]
                         : &g_y[(bz * 256 + (g - 64)) * HW];
    } else {
        dst3 = &g_y[(bz * 256 + 128 + g) * HW];
        dst5 = &g_y[(bz * 256 + 192 + g) * HW];
    }
#pragma unroll
    for (int oy = 0; oy < 4; oy++) {
        int off = (oy0 + py0 + oy) * IMG + ox0 + px0;
        float4 v3 = make_float4(a3[oy][0] + bias3, a3[oy][1] + bias3,
                                a3[oy][2] + bias3, a3[oy][3] + bias3);
        float4 v5 = make_float4(a5[oy][0] + bias5, a5[oy][1] + bias5,
                                a5[oy][2] + bias5, a5[oy][3] + bias5);
        *(float4*)(dst3 + off) = v3;
        *(float4*)(dst5 + off) = v5;
    }
}

// ---------------- gram: per (b,h): G[16][16] = q @ k^T over pixels + sq norms ------
__global__ __launch_bounds__(256) void gram_k()
{
    const int bh = blockIdx.x;           // 0..63
    const int slice = blockIdx.y;        // 0..15 (1024 px each)
    const int b = bh >> 3, h = bh & 7;
    const float* qp = g_q + (long)(b * 128 + h * 16) * HW + slice * 1024;
    const float* kp = g_k + (long)(b * 128 + h * 16) * HW + slice * 1024;

    __shared__ float sq[64][17];
    __shared__ float sk[64][17];
    const int tid = threadIdx.x;
    const int phase = tid & 15, dg = (tid >> 4) & 3, eg = tid >> 6;

    float acc[4][4], aq[4], ak[4];
#pragma unroll
    for (int i = 0; i < 4; i++) {
        aq[i] = 0.f; ak[i] = 0.f;
#pragma unroll
        for (int j = 0; j < 4; j++) acc[i][j] = 0.f;
    }

    for (int blk = 0; blk < 16; ++blk) {
        for (int idx = tid; idx < 1024; idx += 256) {
            int d = idx >> 6, p = idx & 63;
            sq[p][d] = qp[(long)d * HW + blk * 64 + p];
            sk[p][d] = kp[(long)d * HW + blk * 64 + p];
        }
        __syncthreads();
        for (int p = phase; p < 64; p += 16) {
            float qv[4], kv[4];
#pragma unroll
            for (int i = 0; i < 4; i++) qv[i] = sq[p][dg * 4 + i];
#pragma unroll
            for (int j = 0; j < 4; j++) kv[j] = sk[p][eg * 4 + j];
#pragma unroll
            for (int i = 0; i < 4; i++)
#pragma unroll
                for (int j = 0; j < 4; j++) acc[i][j] += qv[i] * kv[j];
            if (eg == 0) {
#pragma unroll
                for (int i = 0; i < 4; i++) aq[i] += qv[i] * qv[i];
            }
            if (dg == 0) {
#pragma unroll
                for (int j = 0; j < 4; j++) ak[j] += kv[j] * kv[j];
            }
        }
        __syncthreads();
    }

    __shared__ float sG[288];
    for (int idx = tid; idx < 288; idx += 256) sG[idx] = 0.f;
    __syncthreads();
#pragma unroll
    for (int i = 0; i < 4; i++)
#pragma unroll
        for (int j = 0; j < 4; j++)
            atomicAdd(&sG[(dg * 4 + i) * 16 + eg * 4 + j], acc[i][j]);
    if (eg == 0) {
#pragma unroll
        for (int i = 0; i < 4; i++) atomicAdd(&sG[256 + dg * 4 + i], aq[i]);
    }
    if (dg == 0) {
#pragma unroll
        for (int j = 0; j < 4; j++) atomicAdd(&sG[272 + eg * 4 + j], ak[j]);
    }
    __syncthreads();
    float* gg = g_gram + bh * 288;
    for (int idx = tid; idx < 288; idx += 256) atomicAdd(gg + idx, sG[idx]);
}

// ---------------- attn: normalize gram, softmax, fold with proj into g_A ----------
__global__ __launch_bounds__(256) void attn_k(
    const float* __restrict__ temp, const float* __restrict__ proj_w)
{
    const int b = blockIdx.x;
    const int part = blockIdx.y;
    const int tid = threadIdx.x;
    float* dstA = g_A + (long)b * 128 * 256;

    if (part == 8) {  // copy proj tail columns (same for all batches)
        for (int idx = tid; idx < 128 * 128; idx += 256) {
            int c = idx >> 7, j = idx & 127;
            dstA[c * 256 + 128 + j] = proj_w[c * 256 + 128 + j];
        }
        return;
    }
    const int h = part;
    const float* gg = g_gram + (b * 8 + h) * 288;
    __shared__ float sA[256], sqn[16], skn[16], srm[16], srs[16];
    if (tid < 16) {
        sqn[tid] = fmaxf(sqrtf(gg[256 + tid]), 1e-12f);
        skn[tid] = fmaxf(sqrtf(gg[272 + tid]), 1e-12f);
    }
    __syncthreads();
    const int d = tid >> 4, e = tid & 15;
    float val = gg[d * 16 + e] / (sqn[d] * skn[e]) * temp[h];
    sA[tid] = val;
    __syncthreads();
    if (e == 0) {
        float m = -1e30f;
        for (int j = 0; j < 16; j++) m = fmaxf(m, sA[d * 16 + j]);
        srm[d] = m;
    }
    __syncthreads();
    float p = expf(val - srm[d]);
    sA[tid] = p;
    __syncthreads();
    if (e == 0) {
        float ssum = 0.f;
        for (int j = 0; j < 16; j++) ssum += sA[d * 16 + j];
        srs[d] = ssum;
    }
    __syncthreads();
    sA[tid] = p / srs[d];
    __syncthreads();
    // fold: A[c][h*16+e] = sum_d proj[c][h*16+d] * attn[d][e]
    for (int o = tid; o < 2048; o += 256) {
        int c = o >> 4, ee = o & 15;
        float accv = 0.f;
#pragma unroll
        for (int dd = 0; dd < 16; dd++)
            accv += proj_w[c * 256 + h * 16 + dd] * sA[dd * 16 + ee];
        dstA[c * 256 + h * 16 + ee] = accv;
    }
}

// ---------------- launch ----------------
extern "C" void kernel_launch(void* const* d_in, const int* in_sizes, int n_in,
                              void* d_out, int out_size)
{
    const float* x      = (const float*)d_in[0];
    const float* pos_w  = (const float*)d_in[1];
    const float* pos_b  = (const float*)d_in[2];
    const float* qd3_w  = (const float*)d_in[3];
    const float* qd3_b  = (const float*)d_in[4];
    const float* qd5_w  = (const float*)d_in[5];
    const float* qd5_b  = (const float*)d_in[6];
    const float* temp   = (const float*)d_in[7];
    const float* d3_w   = (const float*)d_in[8];
    const float* d3_b   = (const float*)d_in[9];
    const float* d5_w   = (const float*)d_in[10];
    const float* d5_b   = (const float*)d_in[11];
    const float* proj_w = (const float*)d_in[12];
    float* out = (float*)d_out;

    zero_gram_k<<<72, 256>>>();
    k1_gemm<<<dim3(128, 3, 8), 256>>>(x, pos_w, pos_b);
    dualconv_k<0><<<dim3(4, 192, 8), 256>>>(nullptr, qd3_w, qd3_b, qd5_w, qd5_b);
    dualconv_k<1><<<dim3(4, 64, 8), 256>>>(x, d3_w, d3_b, d5_w, d5_b);
    gram_k<<<dim3(64, 16), 256>>>();
    attn_k<<<dim3(8, 9), 256>>>(temp, proj_w);
    k4_gemm<<<dim3(128, 1, 8), 256>>>(out);
}